// round 2
// baseline (speedup 1.0000x reference)
#include <cuda_runtime.h>

// Problem constants
#define H 512
#define W 512
#define NC 48          // 16 batch * 3 channels
#define OH 171
#define OW 171
#define TOTAL (NC * OH * OW)   // 1,403,568 output pixels

__global__ void zero_out_kernel(float* out) {
    *out = 0.0f;
}

__global__ void __launch_bounds__(256) ssim_kernel(
    const float* __restrict__ img1,
    const float* __restrict__ img2,
    const float* __restrict__ window,
    float* __restrict__ out)
{
    const float C1 = 0.0001f;   // 0.01^2
    const float C2 = 0.0009f;   // 0.03^2

    // 3x3 gaussian window (same for every channel) — 9 broadcast loads, L1-resident
    float w[9];
    #pragma unroll
    for (int i = 0; i < 9; i++) w[i] = __ldg(window + i);

    float acc = 0.0f;

    const int stride = gridDim.x * blockDim.x;
    for (int idx = blockIdx.x * blockDim.x + threadIdx.x; idx < TOTAL; idx += stride) {
        const int ox    = idx % OW;
        const int t     = idx / OW;
        const int oy    = t % OH;
        const int plane = t / OH;

        const float* __restrict__ p1 = img1 + (size_t)plane * (H * W);
        const float* __restrict__ p2 = img2 + (size_t)plane * (H * W);

        const int ix = 3 * ox - 1;
        const int iy = 3 * oy - 1;

        float mu1 = 0.f, mu2 = 0.f, s11 = 0.f, s22 = 0.f, s12 = 0.f;

        if (ix >= 0 && iy >= 0) {
            // Interior fast path (~98.8% of pixels). Rows/cols 3oy-1..3oy+1 are
            // always in-bounds on the high side (3*170+1 = 511).
            #pragma unroll
            for (int r = 0; r < 3; r++) {
                const float* __restrict__ r1 = p1 + (iy + r) * W + ix;
                const float* __restrict__ r2 = p2 + (iy + r) * W + ix;
                #pragma unroll
                for (int c = 0; c < 3; c++) {
                    const float a  = __ldg(r1 + c);
                    const float b  = __ldg(r2 + c);
                    const float wt = w[r * 3 + c];
                    mu1 += wt * a;
                    mu2 += wt * b;
                    s11 += wt * a * a;
                    s22 += wt * b * b;
                    s12 += wt * a * b;
                }
            }
        } else {
            // Boundary path: only row/col index -1 can occur (zero padding -> skip)
            #pragma unroll
            for (int r = 0; r < 3; r++) {
                const int row = iy + r;
                if (row < 0) continue;
                #pragma unroll
                for (int c = 0; c < 3; c++) {
                    const int col = ix + c;
                    if (col < 0) continue;
                    const float a  = __ldg(p1 + row * W + col);
                    const float b  = __ldg(p2 + row * W + col);
                    const float wt = w[r * 3 + c];
                    mu1 += wt * a;
                    mu2 += wt * b;
                    s11 += wt * a * a;
                    s22 += wt * b * b;
                    s12 += wt * a * b;
                }
            }
        }

        const float m11 = mu1 * mu1;
        const float m22 = mu2 * mu2;
        const float m12 = mu1 * mu2;
        const float v1  = s11 - m11;   // sigma1_sq
        const float v2  = s22 - m22;   // sigma2_sq
        const float v12 = s12 - m12;   // sigma12

        const float num = (2.0f * m12 + C1) * (2.0f * v12 + C2);
        const float den = (m11 + m22 + C1) * (v1 + v2 + C2);
        acc += num / den;
    }

    // Block reduction: warp shuffle -> smem -> warp0 -> one atomic per block
    #pragma unroll
    for (int o = 16; o > 0; o >>= 1)
        acc += __shfl_down_sync(0xffffffffu, acc, o);

    __shared__ float wsum[8];   // 256 threads -> 8 warps
    const int lane = threadIdx.x & 31;
    const int wid  = threadIdx.x >> 5;
    if (lane == 0) wsum[wid] = acc;
    __syncthreads();

    if (wid == 0) {
        acc = (lane < 8) ? wsum[lane] : 0.0f;
        #pragma unroll
        for (int o = 4; o > 0; o >>= 1)
            acc += __shfl_down_sync(0xffffffffu, acc, o);
        if (lane == 0)
            atomicAdd(out, acc * (1.0f / (float)TOTAL));
    }
}

extern "C" void kernel_launch(void* const* d_in, const int* in_sizes, int n_in,
                              void* d_out, int out_size)
{
    const float* img1   = (const float*)d_in[0];
    const float* img2   = (const float*)d_in[1];
    const float* window = (const float*)d_in[2];
    float* out = (float*)d_out;

    zero_out_kernel<<<1, 1>>>(out);

    // ~8 blocks per SM, 256 threads: ~9 pixels per thread (grid-stride)
    const int blocks = 1184;
    ssim_kernel<<<blocks, 256>>>(img1, img2, window, out);
}